// round 17
// baseline (speedup 1.0000x reference)
#include <cuda_runtime.h>

// TaylorExp: out row (273) = [1, x*0.5 (16), outer(sx,sx) (256)]
// sx = x * sqrt(1/(sqrt(2)*sqrt(16)))
//
// Round-17: simplest structure + the session's decisive ingredient.
// One warp per row, direct register->gmem stores with st.global.cs
// (streaming / evict-first): captures the L2 eviction-policy win (R3->R4,
// -8.7us) without smem staging, barriers, fences, or TMA waits.
// Stores have zero reuse, so .cs is pure win (unlike .cs loads, R11).

#define QUAD_SQRT_SCALE 0.42044820762685725f
#define T1_SCALE        0.5f

__global__ void __launch_bounds__(256) taylor_exp_kernel(
    const float* __restrict__ x,
    float* __restrict__ out,
    int rows)
{
    const int gtid = blockIdx.x * blockDim.x + threadIdx.x;
    const int warp = gtid >> 5;
    const int lane = threadIdx.x & 31;
    if (warp >= rows) return;

    const float* __restrict__ xr = x + (size_t)warp * 16;
    float* __restrict__ o = out + (size_t)warp * 273;

    // lanes 0..15 hold the 16 inputs of this row
    float xv = (lane < 16) ? xr[lane] : 0.0f;

    // header: out[0] = 1, out[1..16] = x * 0.5   (streaming stores)
    if (lane < 16)  __stcs(o + 1 + lane, xv * T1_SCALE);
    if (lane == 16) __stcs(o, 1.0f);

    // pre-scaled operand so each quadratic entry is one multiply
    float sx = xv * QUAD_SQRT_SCALE;

    // quadratic block: 256 entries, 8 coalesced 32-lane streaming store waves
    #pragma unroll
    for (int k = 0; k < 8; k++) {
        int q = lane + 32 * k;          // 0..255
        float vr = __shfl_sync(0xffffffffu, sx, q >> 4);
        float vc = __shfl_sync(0xffffffffu, sx, q & 15);
        __stcs(o + 17 + q, vr * vc);
    }
}

extern "C" void kernel_launch(void* const* d_in, const int* in_sizes, int n_in,
                              void* d_out, int out_size)
{
    const float* x = (const float*)d_in[0];
    float* out = (float*)d_out;

    int rows = in_sizes[0] / 16;            // 262144 for the bench shape
    int warps_per_block = 256 / 32;         // 8 rows per block
    int blocks = (rows + warps_per_block - 1) / warps_per_block;

    taylor_exp_kernel<<<blocks, 256>>>(x, out, rows);
}